// round 4
// baseline (speedup 1.0000x reference)
#include <cuda_runtime.h>

#define C_    640
#define HW_   100
#define K2_   9
#define BS_   25
#define BQ_   75
#define R_    128
#define CKK_  5760          // C*K*K
#define SUP_ELEMS (BS_*C_*HW_)   // 1,600,000
#define QRY_ELEMS (BQ_*C_*HW_)   // 4,800,000

// ---------------- scratch (device globals; no allocation) ----------------
__device__ float g_pool_sf[BS_*C_];   // mean over H,W of support
__device__ float g_pool0[BS_*C_];     // ping-pong for pooled conv chain
__device__ float g_pool1[BS_*C_];
__device__ float g_M0[K2_*C_];        // ping-pong for Ws-chain (Ws_eff)
__device__ float g_M1[K2_*C_];
__device__ float g_v0[K2_];           // effective bias for sk_t
__device__ float g_v1[K2_];
__device__ float g_hid[50*R_];        // rows 0..24 = task branch, 25..49 = instance
__device__ float g_ck[50*CKK_];       // channel kernels
__device__ float g_sk[2*BS_*900];     // [0:22500) = sk_t, [22500:) = sk_i (flat raw layout)
__device__ float g_tk[C_*900];        // task kernel [c][p*9+kk]

// ---------------- Kernel A: pooled_sf = mean_hw(support) ----------------
__global__ void pool_kernel(const float* __restrict__ sf) {
    int w = (blockIdx.x * blockDim.x + threadIdx.x) >> 5;
    int lane = threadIdx.x & 31;
    if (w >= BS_*C_) return;
    const float* row = sf + (size_t)w * HW_;
    float s = row[lane] + row[lane+32] + row[lane+64];
    if (lane < 4) s += row[lane+96];
    #pragma unroll
    for (int o = 16; o > 0; o >>= 1) s += __shfl_down_sync(0xffffffffu, s, o);
    if (lane == 0) g_pool_sf[w] = s * 0.01f;
}

// ---------------- chain step: pooled conv chain + Ws_eff chain + bias chain ---
// step s (0..3): pooled uses Wc[s+1]; M-chain uses Wc[4-s] (composed from outside in)
__global__ void chain_step(int step,
                           const float* __restrict__ Wp, const float* __restrict__ bp,
                           const float* __restrict__ Wm, const float* __restrict__ bm,
                           const float* __restrict__ Ws, const float* __restrict__ bs) {
    const float* pin  = (step == 0) ? g_pool_sf : ((step & 1) ? g_pool0 : g_pool1);
    float*       pout = (step & 1) ? g_pool1 : g_pool0;
    const float* Mi   = (step == 0) ? Ws : ((step & 1) ? g_M0 : g_M1);
    float*       Mo   = (step & 1) ? g_M1 : g_M0;
    const float* vi   = (step == 0) ? bs : ((step & 1) ? g_v0 : g_v1);
    float*       vo   = (step & 1) ? g_v1 : g_v0;

    int bid = blockIdx.x;
    if (bid < 80) {
        // pooled part: one warp per output channel o, all 25 batches accumulated
        int o = bid * 8 + (threadIdx.x >> 5);
        int lane = threadIdx.x & 31;
        float acc[BS_];
        #pragma unroll
        for (int b = 0; b < BS_; b++) acc[b] = 0.f;
        for (int c = lane; c < C_; c += 32) {
            float w = Wp[o*C_ + c];
            #pragma unroll
            for (int b = 0; b < BS_; b++) acc[b] += w * pin[b*C_ + c];
        }
        #pragma unroll
        for (int b = 0; b < BS_; b++) {
            float s = acc[b];
            #pragma unroll
            for (int off = 16; off > 0; off >>= 1) s += __shfl_down_sync(0xffffffffu, s, off);
            if (lane == 0) pout[b*C_ + o] = s + bp[o];
        }
    } else if (bid < 103) {
        // M-chain: Mo[k,c] = sum_o Mi[k,o] * Wm[o,c]
        int t = (bid - 80) * 256 + threadIdx.x;
        if (t < K2_*C_) {
            int k = t / C_, c = t % C_;
            const float* mrow = Mi + k*C_;
            float a0 = 0.f, a1 = 0.f, a2 = 0.f, a3 = 0.f;
            for (int o = 0; o < C_; o += 4) {
                a0 += mrow[o+0] * Wm[(o+0)*C_ + c];
                a1 += mrow[o+1] * Wm[(o+1)*C_ + c];
                a2 += mrow[o+2] * Wm[(o+2)*C_ + c];
                a3 += mrow[o+3] * Wm[(o+3)*C_ + c];
            }
            Mo[t] = (a0 + a1) + (a2 + a3);
        }
    } else {
        // bias chain: vo[k] = vi[k] + Mi[k,:] . bm
        int k = (bid - 103) * 8 + (threadIdx.x >> 5);
        int lane = threadIdx.x & 31;
        if (k < K2_) {
            float s = 0.f;
            for (int o = lane; o < C_; o += 32) s += Mi[k*C_ + o] * bm[o];
            #pragma unroll
            for (int off = 16; off > 0; off >>= 1) s += __shfl_down_sync(0xffffffffu, s, off);
            if (lane == 0) vo[k] = vi[k] + s;
        }
    }
}

// ---------------- hidden layer: relu(pooled @ W1 + b1), 50 rows ----------------
__global__ void hid_kernel(const float* __restrict__ W1, const float* __restrict__ b1) {
    int t = blockIdx.x * blockDim.x + threadIdx.x;
    if (t >= 50*R_) return;
    int row = t / R_, r = t % R_;
    const float* src = (row < BS_) ? (g_pool1 + row*C_) : (g_pool_sf + (row-BS_)*C_);
    float acc = 0.f;
    #pragma unroll 8
    for (int c = 0; c < C_; c++) acc += src[c] * W1[c*R_ + r];
    acc += b1[r];
    g_hid[t] = acc > 0.f ? acc : 0.f;
}

// ---------------- channel kernels: hid @ W2 + b2 ----------------
__global__ void ck_kernel(const float* __restrict__ W2, const float* __restrict__ b2) {
    int t = blockIdx.x * blockDim.x + threadIdx.x;
    if (t >= 50*CKK_) return;
    int row = t / CKK_, j = t % CKK_;
    const float* h = g_hid + row*R_;
    float acc = 0.f;
    #pragma unroll 8
    for (int r = 0; r < R_; r++) acc += h[r] * W2[r*CKK_ + j];
    g_ck[t] = acc + b2[j];
}

// ---------------- spatial kernels: sk_t (Ws_eff) and sk_i (Ws) on support ----
__global__ void sk_kernel(const float* __restrict__ sf,
                          const float* __restrict__ Ws, const float* __restrict__ bs) {
    int t = blockIdx.x * blockDim.x + threadIdx.x;
    if (t >= 2*BS_*900) return;
    int variant = t / (BS_*900);   // 0 = task (Ws_eff), 1 = instance (Ws)
    int r = t % (BS_*900);
    int b = r / 900, k = (r % 900) / 100, p = r % 100;
    const float* W = variant ? Ws : g_M1;
    float bias = variant ? bs[k] : g_v1[k];
    const float* x = sf + b*(C_*HW_) + p;
    const float* wr = W + k*C_;
    float acc = 0.f;
    #pragma unroll 8
    for (int c = 0; c < C_; c++) acc += wr[c] * x[c*HW_];
    g_sk[t] = acc + bias;
}

// ---------------- task kernel: mean over support of ck_t ⊗ sk_t ----------------
__global__ void tk_kernel() {
    int t = blockIdx.x * blockDim.x + threadIdx.x;
    if (t >= C_*900) return;
    int c = t / 900, t9 = t % 900, kk = t9 % 9;
    float acc = 0.f;
    #pragma unroll
    for (int b = 0; b < BS_; b++)
        acc += g_ck[b*CKK_ + c*9 + kk] * g_sk[b*900 + t9];
    g_tk[t] = acc * (1.f / BS_);
}

// ---------------- involution (support, fused kernel) ----------------
__global__ void inv_support(const float* __restrict__ sf, float* __restrict__ out) {
    int t = blockIdx.x * blockDim.x + threadIdx.x;
    if (t >= SUP_ELEMS) return;
    int b = t / (C_*HW_);
    int rem = t % (C_*HW_);
    int c = rem / HW_, p = rem % HW_;
    int i = p / 10, j = p % 10;
    const float* x   = sf + b*(C_*HW_) + c*HW_;
    const float* cki = g_ck + (BS_ + b)*CKK_ + c*9;
    const float* ski = g_sk + BS_*900 + b*900 + p*9;
    const float* tkp = g_tk + c*900 + p*9;
    float acc = 0.f;
    #pragma unroll
    for (int u = 0; u < 3; u++) {
        int ii = i + u - 1;
        if (ii < 0 || ii >= 10) continue;
        #pragma unroll
        for (int v = 0; v < 3; v++) {
            int jj = j + v - 1;
            if (jj < 0 || jj >= 10) continue;
            int kk = u*3 + v;
            acc += cki[kk] * ski[kk] * tkp[kk] * x[ii*10 + jj];
        }
    }
    out[t] = acc;
}

// ---------------- involution (query, task kernel broadcast) ----------------
__global__ void inv_query(const float* __restrict__ qf, float* __restrict__ out) {
    int t = blockIdx.x * blockDim.x + threadIdx.x;
    if (t >= QRY_ELEMS) return;
    int b = t / (C_*HW_);
    int rem = t % (C_*HW_);
    int c = rem / HW_, p = rem % HW_;
    int i = p / 10, j = p % 10;
    const float* x   = qf + b*(C_*HW_) + c*HW_;
    const float* tkp = g_tk + c*900 + p*9;
    float acc = 0.f;
    #pragma unroll
    for (int u = 0; u < 3; u++) {
        int ii = i + u - 1;
        if (ii < 0 || ii >= 10) continue;
        #pragma unroll
        for (int v = 0; v < 3; v++) {
            int jj = j + v - 1;
            if (jj < 0 || jj >= 10) continue;
            acc += tkp[u*3 + v] * x[ii*10 + jj];
        }
    }
    out[t] = acc;
}

extern "C" void kernel_launch(void* const* d_in, const int* in_sizes, int n_in,
                              void* d_out, int out_size) {
    const float* sf  = (const float*)d_in[0];
    const float* qf  = (const float*)d_in[1];
    const float* Wc[4] = { (const float*)d_in[2], (const float*)d_in[4],
                           (const float*)d_in[6], (const float*)d_in[8] };
    const float* bc[4] = { (const float*)d_in[3], (const float*)d_in[5],
                           (const float*)d_in[7], (const float*)d_in[9] };
    const float* W1 = (const float*)d_in[10];
    const float* b1 = (const float*)d_in[11];
    const float* W2 = (const float*)d_in[12];
    const float* b2 = (const float*)d_in[13];
    const float* Ws = (const float*)d_in[14];
    const float* bs = (const float*)d_in[15];
    float* out = (float*)d_out;

    // A: pooled support means (16000 warps)
    pool_kernel<<<2000, 256>>>(sf);

    // 4 fused chain steps: pooled conv chain (inside-out) + Ws_eff chain (outside-in)
    for (int s = 0; s < 4; s++) {
        chain_step<<<105, 256>>>(s, Wc[s], bc[s], Wc[3-s], bc[3-s], Ws, bs);
    }

    // channel-branch MLP for both task (pooled_t) and instance (pooled_sf) rows
    hid_kernel<<<(50*R_ + 255)/256, 256>>>(W1, b1);
    ck_kernel<<<(50*CKK_ + 255)/256, 256>>>(W2, b2);

    // spatial kernels (both variants in one launch)
    sk_kernel<<<(2*BS_*900 + 255)/256, 256>>>(sf, Ws, bs);

    // task kernel
    tk_kernel<<<(C_*900 + 255)/256, 256>>>();

    // involutions -> output (support first, then query)
    inv_support<<<(SUP_ELEMS + 255)/256, 256>>>(sf, out);
    inv_query<<<(QRY_ELEMS + 255)/256, 256>>>(qf, out + SUP_ELEMS);
}

// round 9
// speedup vs baseline: 1.1844x; 1.1844x over previous
#include <cuda_runtime.h>

#define C_    640
#define HW_   100
#define K2_   9
#define BS_   25
#define BQ_   75
#define R_    128
#define CKK_  5760          // C*K*K
#define SUP_ELEMS (BS_*C_*HW_)   // 1,600,000
#define QRY_ELEMS (BQ_*C_*HW_)   // 4,800,000

// ---------------- scratch (device globals; no allocation) ----------------
__device__ float g_pool_sf[BS_*C_];       // mean over H,W of support
__device__ float g_pp[2][10][BS_*C_];     // ping-pong partial pooled chain (10 c-chunks)
__device__ float g_mp[2][10][K2_*C_];     // ping-pong partial Ws_eff chain
__device__ float g_vv[2][K2_];            // effective-bias chain
__device__ float g_pool_f[BS_*C_];        // finalized pooled (after 4 convs)
__device__ float g_M_f[K2_*C_];           // finalized Ws_eff
__device__ float g_hid[50*R_];            // rows 0..24 = task branch, 25..49 = instance
__device__ float g_ck[50*CKK_];           // channel kernels
__device__ float g_sk[2*BS_*900];         // [0:22500) = sk_t, [22500:) = sk_i (flat raw layout)
__device__ float g_tk[C_*900];            // task kernel [c][p*9+kk]

// ---------------- Kernel A: pooled_sf = mean_hw(support) ----------------
__global__ void pool_kernel(const float* __restrict__ sf) {
    int w = (blockIdx.x * blockDim.x + threadIdx.x) >> 5;
    int lane = threadIdx.x & 31;
    if (w >= BS_*C_) return;
    const float* row = sf + (size_t)w * HW_;
    float s = row[lane] + row[lane+32] + row[lane+64];
    if (lane < 4) s += row[lane+96];
    #pragma unroll
    for (int o = 16; o > 0; o >>= 1) s += __shfl_down_sync(0xffffffffu, s, o);
    if (lane == 0) g_pool_sf[w] = s * 0.01f;
}

// ---------------- chain step (tiled-GEMM, reduction split into 10 chunks) ----
// step s (0..3): pooled uses Wp=Wc[s]; M-chain uses Wm=Wc[3-s] (composed outside-in)
// Outputs are 10 partial sums (one per 64-wide reduction chunk) -> no atomics,
// deterministic, and 301 blocks of parallelism per step.
__global__ void chain_step(int step,
                           const float* __restrict__ Wp, const float* __restrict__ bp,
                           const float* __restrict__ Wm, const float* __restrict__ bm,
                           const float* __restrict__ Ws, const float* __restrict__ bs) {
    __shared__ float sm[4672];   // A: 1600 + 64*33 = 3712 ; B: 576 + 4096 = 4672
    const int bid = blockIdx.x, tid = threadIdx.x;
    const int out = step & 1;
    const int in  = (step - 1) & 1;      // valid only for step > 0
    const bool first = (step == 0);

    if (bid < 200) {
        // -------- pooled GEMM: pout[b,o] = sum_c pin[b,c]*Wp[o,c] (+bp in q==0)
        const int t = bid / 10;          // o-tile (32 outputs)
        const int q = bid % 10;          // c-chunk (64 reduction elems)
        float* s_pin = sm;               // [25][64]
        float* s_wp  = sm + 1600;        // [64][33]  (transposed, padded)
        for (int i = tid; i < 1600; i += 256) {
            int b = i >> 6, c = i & 63;
            int gidx = b*C_ + q*64 + c;
            float v;
            if (first) v = g_pool_sf[gidx];
            else {
                v = 0.f;
                #pragma unroll
                for (int qq = 0; qq < 10; qq++) v += g_pp[in][qq][gidx];
            }
            s_pin[i] = v;
        }
        for (int i = tid; i < 2048; i += 256) {
            int o = i >> 6, c = i & 63;
            s_wp[c*33 + o] = Wp[(t*32 + o)*C_ + q*64 + c];
        }
        __syncthreads();
        int ol = tid & 31, bg = tid >> 5;
        int og = t*32 + ol;
        for (int b = bg; b < 25; b += 8) {
            float acc = (q == 0) ? bp[og] : 0.f;
            #pragma unroll
            for (int c = 0; c < 64; c++) acc += s_pin[b*64 + c] * s_wp[c*33 + ol];
            g_pp[out][q][b*C_ + og] = acc;
        }
    } else if (bid < 300) {
        // -------- M-chain GEMM: Mo[k,c] = sum_o Mi[k,o]*Wm[o,c]
        const int ct = (bid - 200) / 10;  // c-tile (64 outputs)
        const int q  = (bid - 200) % 10;  // o-chunk (64 reduction elems)
        float* s_mi = sm;                 // [9][64]
        float* s_wm = sm + 576;           // [64][64]
        for (int i = tid; i < 576; i += 256) {
            int k = i >> 6, o = i & 63;
            int gidx = k*C_ + q*64 + o;
            float v;
            if (first) v = Ws[gidx];
            else {
                v = 0.f;
                #pragma unroll
                for (int qq = 0; qq < 10; qq++) v += g_mp[in][qq][gidx];
            }
            s_mi[i] = v;
        }
        for (int i = tid; i < 4096; i += 256) {
            int o = i >> 6, c = i & 63;
            s_wm[i] = Wm[(q*64 + o)*C_ + ct*64 + c];
        }
        __syncthreads();
        int cl = tid & 63, kg = tid >> 6;
        for (int k = kg; k < 9; k += 4) {
            float acc = 0.f;
            #pragma unroll
            for (int o = 0; o < 64; o++) acc += s_mi[k*64 + o] * s_wm[o*64 + cl];
            g_mp[out][q][k*C_ + ct*64 + cl] = acc;
        }
    } else {
        // -------- bias chain: vo[k] = vi[k] + Mi[k,:] . bm
        int k = tid >> 5, lane = tid & 31;
        if (k < K2_) {
            float s = 0.f;
            for (int o = lane; o < C_; o += 32) {
                int gidx = k*C_ + o;
                float mi;
                if (first) mi = Ws[gidx];
                else {
                    mi = 0.f;
                    #pragma unroll
                    for (int qq = 0; qq < 10; qq++) mi += g_mp[in][qq][gidx];
                }
                s += mi * bm[o];
            }
            #pragma unroll
            for (int off = 16; off > 0; off >>= 1) s += __shfl_down_sync(0xffffffffu, s, off);
            if (lane == 0) {
                float vi = first ? bs[k] : g_vv[in][k];
                g_vv[out][k] = vi + s;
            }
        }
    }
}

// ---------------- finalize: collapse the 10 partials of the last step ----------
__global__ void finalize_kernel() {
    int t = blockIdx.x * blockDim.x + threadIdx.x;
    if (t < BS_*C_) {
        float s = 0.f;
        #pragma unroll
        for (int q = 0; q < 10; q++) s += g_pp[1][q][t];
        g_pool_f[t] = s;
    } else if (t < BS_*C_ + K2_*C_) {
        int i = t - BS_*C_;
        float s = 0.f;
        #pragma unroll
        for (int q = 0; q < 10; q++) s += g_mp[1][q][i];
        g_M_f[i] = s;
    }
}

// ---------------- hidden layer: relu(pooled @ W1 + b1), 50 rows ----------------
__global__ void hid_kernel(const float* __restrict__ W1, const float* __restrict__ b1) {
    int t = blockIdx.x * blockDim.x + threadIdx.x;
    if (t >= 50*R_) return;
    int row = t / R_, r = t % R_;
    const float* src = (row < BS_) ? (g_pool_f + row*C_) : (g_pool_sf + (row-BS_)*C_);
    float acc = 0.f;
    #pragma unroll 8
    for (int c = 0; c < C_; c++) acc += src[c] * W1[c*R_ + r];
    acc += b1[r];
    g_hid[t] = acc > 0.f ? acc : 0.f;
}

// ---------------- channel kernels: hid @ W2 + b2 ----------------
__global__ void ck_kernel(const float* __restrict__ W2, const float* __restrict__ b2) {
    int t = blockIdx.x * blockDim.x + threadIdx.x;
    if (t >= 50*CKK_) return;
    int row = t / CKK_, j = t % CKK_;
    const float* h = g_hid + row*R_;
    float acc = 0.f;
    #pragma unroll 8
    for (int r = 0; r < R_; r++) acc += h[r] * W2[r*CKK_ + j];
    g_ck[t] = acc + b2[j];
}

// ---------------- spatial kernels: all 9 k-rows fused per thread ----------------
__global__ void sk_kernel(const float* __restrict__ sf,
                          const float* __restrict__ Ws, const float* __restrict__ bs) {
    int t = blockIdx.x * blockDim.x + threadIdx.x;
    if (t >= 2*BS_*HW_) return;        // 5000 threads
    int variant = t / (BS_*HW_);       // 0 = task (Ws_eff), 1 = instance (Ws)
    int r = t % (BS_*HW_);
    int b = r / HW_, p = r % HW_;
    const float* W = variant ? Ws : g_M_f;
    const float* x = sf + b*(C_*HW_) + p;
    float acc[K2_];
    #pragma unroll
    for (int k = 0; k < K2_; k++) acc[k] = variant ? bs[k] : g_vv[1][k];
    #pragma unroll 4
    for (int c = 0; c < C_; c++) {
        float xv = x[c*HW_];
        #pragma unroll
        for (int k = 0; k < K2_; k++) acc[k] += W[k*C_ + c] * xv;
    }
    float* dst = g_sk + variant*(BS_*900) + b*900;
    #pragma unroll
    for (int k = 0; k < K2_; k++) dst[k*100 + p] = acc[k];
}

// ---------------- task kernel: mean over support of ck_t ⊗ sk_t ----------------
__global__ void tk_kernel() {
    int t = blockIdx.x * blockDim.x + threadIdx.x;
    if (t >= C_*900) return;
    int c = t / 900, t9 = t % 900, kk = t9 % 9;
    float acc = 0.f;
    #pragma unroll
    for (int b = 0; b < BS_; b++)
        acc += g_ck[b*CKK_ + c*9 + kk] * g_sk[b*900 + t9];
    g_tk[t] = acc * (1.f / BS_);
}

// ---------------- involution (support, fused kernel) ----------------
__global__ void inv_support(const float* __restrict__ sf, float* __restrict__ out) {
    int t = blockIdx.x * blockDim.x + threadIdx.x;
    if (t >= SUP_ELEMS) return;
    int b = t / (C_*HW_);
    int rem = t % (C_*HW_);
    int c = rem / HW_, p = rem % HW_;
    int i = p / 10, j = p % 10;
    const float* x   = sf + b*(C_*HW_) + c*HW_;
    const float* cki = g_ck + (BS_ + b)*CKK_ + c*9;
    const float* ski = g_sk + BS_*900 + b*900 + p*9;
    const float* tkp = g_tk + c*900 + p*9;
    float acc = 0.f;
    #pragma unroll
    for (int u = 0; u < 3; u++) {
        int ii = i + u - 1;
        if (ii < 0 || ii >= 10) continue;
        #pragma unroll
        for (int v = 0; v < 3; v++) {
            int jj = j + v - 1;
            if (jj < 0 || jj >= 10) continue;
            int kk = u*3 + v;
            acc += cki[kk] * ski[kk] * tkp[kk] * x[ii*10 + jj];
        }
    }
    out[t] = acc;
}

// ---------------- involution (query, task kernel broadcast) ----------------
__global__ void inv_query(const float* __restrict__ qf, float* __restrict__ out) {
    int t = blockIdx.x * blockDim.x + threadIdx.x;
    if (t >= QRY_ELEMS) return;
    int b = t / (C_*HW_);
    int rem = t % (C_*HW_);
    int c = rem / HW_, p = rem % HW_;
    int i = p / 10, j = p % 10;
    const float* x   = qf + b*(C_*HW_) + c*HW_;
    const float* tkp = g_tk + c*900 + p*9;
    float acc = 0.f;
    #pragma unroll
    for (int u = 0; u < 3; u++) {
        int ii = i + u - 1;
        if (ii < 0 || ii >= 10) continue;
        #pragma unroll
        for (int v = 0; v < 3; v++) {
            int jj = j + v - 1;
            if (jj < 0 || jj >= 10) continue;
            acc += tkp[u*3 + v] * x[ii*10 + jj];
        }
    }
    out[t] = acc;
}

extern "C" void kernel_launch(void* const* d_in, const int* in_sizes, int n_in,
                              void* d_out, int out_size) {
    const float* sf  = (const float*)d_in[0];
    const float* qf  = (const float*)d_in[1];
    const float* Wc[4] = { (const float*)d_in[2], (const float*)d_in[4],
                           (const float*)d_in[6], (const float*)d_in[8] };
    const float* bc[4] = { (const float*)d_in[3], (const float*)d_in[5],
                           (const float*)d_in[7], (const float*)d_in[9] };
    const float* W1 = (const float*)d_in[10];
    const float* b1 = (const float*)d_in[11];
    const float* W2 = (const float*)d_in[12];
    const float* b2 = (const float*)d_in[13];
    const float* Ws = (const float*)d_in[14];
    const float* bs = (const float*)d_in[15];
    float* out = (float*)d_out;

    // pooled support means
    pool_kernel<<<2000, 256>>>(sf);

    // 4 tiled chain steps: pooled conv chain (inside-out) + Ws_eff chain (outside-in)
    for (int s = 0; s < 4; s++) {
        chain_step<<<301, 256>>>(s, Wc[s], bc[s], Wc[3-s], bc[3-s], Ws, bs);
    }
    finalize_kernel<<<(BS_*C_ + K2_*C_ + 255)/256, 256>>>();

    // channel-branch MLP for both task (pooled_f) and instance (pooled_sf) rows
    hid_kernel<<<(50*R_ + 255)/256, 256>>>(W1, b1);
    ck_kernel<<<(50*CKK_ + 255)/256, 256>>>(W2, b2);

    // spatial kernels (both variants, 9 rows fused per thread)
    sk_kernel<<<(2*BS_*HW_ + 255)/256, 256>>>(sf, Ws, bs);

    // task kernel
    tk_kernel<<<(C_*900 + 255)/256, 256>>>();

    // involutions -> output (support first, then query)
    inv_support<<<(SUP_ELEMS + 255)/256, 256>>>(sf, out);
    inv_query<<<(QRY_ELEMS + 255)/256, 256>>>(qf, out + SUP_ELEMS);
}